// round 13
// baseline (speedup 1.0000x reference)
#include <cuda_runtime.h>
#include <cuda_fp16.h>
#include <cstdint>

// ===================== problem dims =====================
#define TOK    8192
#define HID    4096
#define KACT   3302
#define KPAD   3328      // 52 * 64
#define WFULL  11008
#define NCH1   64        // 4096 / 64
#define NCH2   52        // 3328 / 64

// ===================== device scratch (static, no allocs) =====================
__device__ __half g_x  [(size_t)TOK * HID];
__device__ __half g_wgu[(size_t)2 * KPAD * HID];   // rows interleaved: 2j=gate_j, 2j+1=up_j
__device__ __half g_wd [(size_t)HID * KPAD];
__device__ __half g_h  [(size_t)TOK * KPAD];

// ===================== low-level helpers =====================
__device__ __forceinline__ uint32_t smem_u32(const void* p) {
    uint32_t a;
    asm("{ .reg .u64 t; cvta.to.shared.u64 t, %1; cvt.u32.u64 %0, t; }" : "=r"(a) : "l"(p));
    return a;
}
__device__ __forceinline__ uint32_t swz(uint32_t off) {   // SW128: bits[6:4] ^= bits[9:7]
    return off ^ ((off >> 3) & 0x70);
}
#define CP_COMMIT() asm volatile("cp.async.commit_group;" ::: "memory")
#define CP_WAIT1()  asm volatile("cp.async.wait_group 1;" ::: "memory")

__device__ __forceinline__ void cp16(uint32_t d, const void* s) {
    asm volatile("cp.async.cg.shared.global [%0], [%1], 16;" :: "r"(d), "l"(s));
}

// Load ROWS x 64 fp16 K-major tile into SW128 smem with cp.async (NT threads)
template<int ROWS, int NT>
__device__ __forceinline__ void cp_tile(uint32_t dbase, const __half* __restrict__ src, int ld) {
#pragma unroll
    for (int it = 0; it < (ROWS * 8) / NT; ++it) {
        int i = threadIdx.x + it * NT;
        int row = i >> 3, c = i & 7;
        uint32_t off = (uint32_t)(row * 128 + c * 16);
        cp16(dbase + swz(off), src + (size_t)row * ld + c * 8);
    }
}

__device__ __forceinline__ void ldsm_x4(uint32_t* r, uint32_t addr) {
    asm volatile("ldmatrix.sync.aligned.m8n8.x4.shared.b16 {%0,%1,%2,%3}, [%4];"
                 : "=r"(r[0]), "=r"(r[1]), "=r"(r[2]), "=r"(r[3]) : "r"(addr));
}

// fp16-accumulator MMA: D(f16x2 x2) = A*B + C
__device__ __forceinline__ void mma_f16a(uint32_t* c, const uint32_t* a, uint32_t b0, uint32_t b1) {
    asm volatile("mma.sync.aligned.m16n8k16.row.col.f16.f16.f16.f16 "
                 "{%0,%1}, {%2,%3,%4,%5}, {%6,%7}, {%0,%1};"
                 : "+r"(c[0]), "+r"(c[1])
                 : "r"(a[0]), "r"(a[1]), "r"(a[2]), "r"(a[3]), "r"(b0), "r"(b1));
}

// ===================== convert kernels =====================
__global__ void __launch_bounds__(256) conv_x_kernel(const float* __restrict__ x) {
    int idx4 = (blockIdx.x * 256 + threadIdx.x) * 4;
    float4 f = *reinterpret_cast<const float4*>(x + idx4);
    __half h[4] = {__float2half(f.x), __float2half(f.y), __float2half(f.z), __float2half(f.w)};
    *reinterpret_cast<uint2*>(g_x + idx4) = *reinterpret_cast<const uint2*>(h);
}

__global__ void __launch_bounds__(256) conv_gu_kernel(const float* __restrict__ Wg,
                                                      const float* __restrict__ Wu,
                                                      const int* __restrict__ aidx) {
    int idx4 = (blockIdx.x * 256 + threadIdx.x) * 4;   // < KPAD*HID
    int r = idx4 >> 12;
    int c = idx4 & 4095;
    __half hg[4] = {__half(0.f), __half(0.f), __half(0.f), __half(0.f)};
    __half hu[4] = {__half(0.f), __half(0.f), __half(0.f), __half(0.f)};
    if (r < KACT) {
        int a = aidx[r];
        float4 fg = *reinterpret_cast<const float4*>(Wg + (size_t)a * HID + c);
        float4 fu = *reinterpret_cast<const float4*>(Wu + (size_t)a * HID + c);
        hg[0] = __float2half(fg.x); hg[1] = __float2half(fg.y);
        hg[2] = __float2half(fg.z); hg[3] = __float2half(fg.w);
        hu[0] = __float2half(fu.x); hu[1] = __float2half(fu.y);
        hu[2] = __float2half(fu.z); hu[3] = __float2half(fu.w);
    }
    // interleaved rows: 2r = gate, 2r+1 = up
    *reinterpret_cast<uint2*>(g_wgu + (size_t)(2 * r) * HID + c)     = *reinterpret_cast<const uint2*>(hg);
    *reinterpret_cast<uint2*>(g_wgu + (size_t)(2 * r + 1) * HID + c) = *reinterpret_cast<const uint2*>(hu);
}

__global__ void __launch_bounds__(256) conv_wd_kernel(const float* __restrict__ Wd,
                                                      const int* __restrict__ aidx) {
    int idx4 = (blockIdx.x * 256 + threadIdx.x) * 4;   // < HID*KPAD
    int hh = idx4 / KPAD;
    int r  = idx4 - hh * KPAD;
    __half v[4];
#pragma unroll
    for (int j = 0; j < 4; ++j) {
        int k = r + j;
        v[j] = (k < KACT) ? __float2half(Wd[(size_t)hh * WFULL + aidx[k]]) : __half(0.f);
    }
    *reinterpret_cast<uint2*>(g_wd + idx4) = *reinterpret_cast<const uint2*>(v);
}

// ===================== GEMM core config =====================
// CTA 64x128, 128 threads, 4 warps (warp tile 32x64). K-chunk 64, 3-stage cp.async,
// 3 CTAs/SM. fp16-ACCUMULATOR MMA within each K=64 chunk, promoted to fp32
// master accumulators at chunk end (bounds fp16 rounding exposure to 4 adds).
// Stage: A@0 (8K, 64 rows), B@8K (16K, 128 rows) = 24K. 3 stages = 72K/CTA.
#define STG      24576
#define SMEM_REQ (3 * STG + 1024)

// ===================== GEMM1: h = silu(x Wg^T) * (x Wu^T), interleaved B =====================
// grid (128, 52).
__global__ void __launch_bounds__(128, 3) gemm1_kernel() {
    extern __shared__ char smem_raw[];
    char* smem = (char*)(((uintptr_t)smem_raw + 1023) & ~(uintptr_t)1023);
    uint32_t sb = smem_u32(smem);
    const int tid = threadIdx.x, l = tid & 31, wid = tid >> 5;
    const int wm = wid & 1, wn = wid >> 1;
    const int bM = blockIdx.x, bN = blockIdx.y;

    const __half* A = g_x   + (size_t)bM * 64 * HID;
    const __half* B = g_wgu + (size_t)bN * 128 * HID;

    float acc[2][8][4] = {};

    auto load_stage = [&](int ch, int s) {
        uint32_t base = sb + s * STG;
        cp_tile<64, 128>(base +    0, A + ch * 64, HID);
        cp_tile<128, 128>(base + 8192, B + ch * 64, HID);
    };

    load_stage(0, 0); CP_COMMIT();
    load_stage(1, 1); CP_COMMIT();

    for (int ch = 0; ch < NCH1; ++ch) {
        CP_WAIT1();
        __syncthreads();
        if (ch + 2 < NCH1) { load_stage(ch + 2, (ch + 2) % 3); CP_COMMIT(); }
        uint32_t base = sb + (ch % 3) * STG;

        uint32_t cacc[2][8][2] = {};   // fp16x2 chunk accumulators (zeroed each chunk)

#pragma unroll
        for (int kk = 0; kk < 4; ++kk) {
            uint32_t a[2][4];
#pragma unroll
            for (int mi = 0; mi < 2; ++mi) {
                uint32_t off = (uint32_t)((wm * 32 + mi * 16 + (l & 15)) * 128 + (kk * 2 + (l >> 4)) * 16);
                ldsm_x4(a[mi], base + swz(off));
            }
            uint32_t b[4][4];
#pragma unroll
            for (int g4 = 0; g4 < 4; ++g4) {
                uint32_t off = (uint32_t)((wn * 64 + g4 * 16 + (l & 15)) * 128 + (kk * 2 + (l >> 4)) * 16);
                ldsm_x4(b[g4], base + 8192 + swz(off));
            }
#pragma unroll
            for (int mi = 0; mi < 2; ++mi)
#pragma unroll
                for (int g4 = 0; g4 < 4; ++g4)
#pragma unroll
                    for (int h = 0; h < 2; ++h)
                        mma_f16a(cacc[mi][g4 * 2 + h], a[mi], b[g4][h], b[g4][2 + h]);
        }

        // promote chunk accumulators into fp32 masters
#pragma unroll
        for (int mi = 0; mi < 2; ++mi)
#pragma unroll
            for (int nj = 0; nj < 8; ++nj) {
                float2 lo = __half22float2(*reinterpret_cast<__half2*>(&cacc[mi][nj][0]));
                float2 hi = __half22float2(*reinterpret_cast<__half2*>(&cacc[mi][nj][1]));
                acc[mi][nj][0] += lo.x; acc[mi][nj][1] += lo.y;
                acc[mi][nj][2] += hi.x; acc[mi][nj][3] += hi.y;
            }
    }

    // Epilogue: thread frag cols are (gate, up) pairs -> silu fused locally.
#pragma unroll
    for (int mi = 0; mi < 2; ++mi)
#pragma unroll
        for (int nj = 0; nj < 8; ++nj) {
            int r  = bM * 64 + wm * 32 + mi * 16 + (l >> 2);
            int hc = bN * 64 + wn * 32 + nj * 4 + (l & 3);
            float g0 = acc[mi][nj][0], u0 = acc[mi][nj][1];
            float g1 = acc[mi][nj][2], u1 = acc[mi][nj][3];
            float h0 = u0 * g0 / (1.f + __expf(-g0));
            float h1 = u1 * g1 / (1.f + __expf(-g1));
            g_h[(size_t)r * KPAD + hc]       = __float2half(h0);
            g_h[(size_t)(r + 8) * KPAD + hc] = __float2half(h1);
        }
}

// ===================== GEMM2: out = h Wd^T =====================
// grid (128, 32).
__global__ void __launch_bounds__(128, 3) gemm2_kernel(float* __restrict__ out) {
    extern __shared__ char smem_raw[];
    char* smem = (char*)(((uintptr_t)smem_raw + 1023) & ~(uintptr_t)1023);
    uint32_t sb = smem_u32(smem);
    const int tid = threadIdx.x, l = tid & 31, wid = tid >> 5;
    const int wm = wid & 1, wn = wid >> 1;
    const int bM = blockIdx.x, bN = blockIdx.y;

    const __half* A = g_h  + (size_t)bM * 64 * KPAD;
    const __half* B = g_wd + (size_t)bN * 128 * KPAD;

    float acc[2][8][4] = {};

    auto load_stage = [&](int ch, int s) {
        uint32_t base = sb + s * STG;
        cp_tile<64, 128>(base +    0, A + ch * 64, KPAD);
        cp_tile<128, 128>(base + 8192, B + ch * 64, KPAD);
    };

    load_stage(0, 0); CP_COMMIT();
    load_stage(1, 1); CP_COMMIT();

    for (int ch = 0; ch < NCH2; ++ch) {
        CP_WAIT1();
        __syncthreads();
        if (ch + 2 < NCH2) { load_stage(ch + 2, (ch + 2) % 3); CP_COMMIT(); }
        uint32_t base = sb + (ch % 3) * STG;

        uint32_t cacc[2][8][2] = {};

#pragma unroll
        for (int kk = 0; kk < 4; ++kk) {
            uint32_t a[2][4];
#pragma unroll
            for (int mi = 0; mi < 2; ++mi) {
                uint32_t off = (uint32_t)((wm * 32 + mi * 16 + (l & 15)) * 128 + (kk * 2 + (l >> 4)) * 16);
                ldsm_x4(a[mi], base + swz(off));
            }
            uint32_t b[4][4];
#pragma unroll
            for (int g4 = 0; g4 < 4; ++g4) {
                uint32_t off = (uint32_t)((wn * 64 + g4 * 16 + (l & 15)) * 128 + (kk * 2 + (l >> 4)) * 16);
                ldsm_x4(b[g4], base + 8192 + swz(off));
            }
#pragma unroll
            for (int mi = 0; mi < 2; ++mi)
#pragma unroll
                for (int g4 = 0; g4 < 4; ++g4)
#pragma unroll
                    for (int h = 0; h < 2; ++h)
                        mma_f16a(cacc[mi][g4 * 2 + h], a[mi], b[g4][h], b[g4][2 + h]);
        }

#pragma unroll
        for (int mi = 0; mi < 2; ++mi)
#pragma unroll
            for (int nj = 0; nj < 8; ++nj) {
                float2 lo = __half22float2(*reinterpret_cast<__half2*>(&cacc[mi][nj][0]));
                float2 hi = __half22float2(*reinterpret_cast<__half2*>(&cacc[mi][nj][1]));
                acc[mi][nj][0] += lo.x; acc[mi][nj][1] += lo.y;
                acc[mi][nj][2] += hi.x; acc[mi][nj][3] += hi.y;
            }
    }

    // Epilogue: fp32 float2 stores.
#pragma unroll
    for (int mi = 0; mi < 2; ++mi)
#pragma unroll
        for (int nj = 0; nj < 8; ++nj) {
            int r = bM * 64 + wm * 32 + mi * 16 + (l >> 2);
            int c = bN * 128 + wn * 64 + nj * 8 + (l & 3) * 2;
            float2 v0; v0.x = acc[mi][nj][0]; v0.y = acc[mi][nj][1];
            float2 v1; v1.x = acc[mi][nj][2]; v1.y = acc[mi][nj][3];
            *reinterpret_cast<float2*>(out + (size_t)r * HID + c) = v0;
            *reinterpret_cast<float2*>(out + (size_t)(r + 8) * HID + c) = v1;
        }
}

// ===================== launch =====================
extern "C" void kernel_launch(void* const* d_in, const int* in_sizes, int n_in,
                              void* d_out, int out_size) {
    const float* x  = (const float*)d_in[0];
    const float* Wg = (const float*)d_in[1];
    const float* Wu = (const float*)d_in[2];
    const float* Wd = (const float*)d_in[3];
    const int* aidx = (const int*)d_in[4];
    float* out = (float*)d_out;

    cudaFuncSetAttribute(gemm1_kernel, cudaFuncAttributeMaxDynamicSharedMemorySize, SMEM_REQ);
    cudaFuncSetAttribute(gemm2_kernel, cudaFuncAttributeMaxDynamicSharedMemorySize, SMEM_REQ);

    conv_x_kernel<<<(TOK * (size_t)HID) / 1024, 256>>>(x);
    conv_gu_kernel<<<((size_t)KPAD * HID) / 1024, 256>>>(Wg, Wu, aidx);
    conv_wd_kernel<<<((size_t)HID * KPAD) / 1024, 256>>>(Wd, aidx);
    gemm1_kernel<<<dim3(128, 52), 128, SMEM_REQ>>>();
    gemm2_kernel<<<dim3(128, 32), 128, SMEM_REQ>>>(out);
}

// round 14
// speedup vs baseline: 1.1322x; 1.1322x over previous
#include <cuda_runtime.h>
#include <cuda_fp16.h>
#include <cstdint>

// ===================== problem dims =====================
#define TOK    8192
#define HID    4096
#define KACT   3302
#define KPAD   3328      // 52 * 64
#define WFULL  11008
#define NCH1   64        // 4096 / 64
#define NCH2   52        // 3328 / 64

// ===================== device scratch (static, no allocs) =====================
__device__ __half g_x [(size_t)TOK * HID];
__device__ __half g_wg[(size_t)KPAD * HID];
__device__ __half g_wu[(size_t)KPAD * HID];
__device__ __half g_wd[(size_t)HID * KPAD];
__device__ __half g_h [(size_t)TOK * KPAD];

// ===================== low-level helpers =====================
__device__ __forceinline__ uint32_t smem_u32(const void* p) {
    uint32_t a;
    asm("{ .reg .u64 t; cvta.to.shared.u64 t, %1; cvt.u32.u64 %0, t; }" : "=r"(a) : "l"(p));
    return a;
}
__device__ __forceinline__ uint32_t swz(uint32_t off) {   // SW128: bits[6:4] ^= bits[9:7]
    return off ^ ((off >> 3) & 0x70);
}
#define CP_COMMIT() asm volatile("cp.async.commit_group;" ::: "memory")
#define CP_WAIT1()  asm volatile("cp.async.wait_group 1;" ::: "memory")

__device__ __forceinline__ void cp16(uint32_t d, const void* s) {
    asm volatile("cp.async.cg.shared.global [%0], [%1], 16;" :: "r"(d), "l"(s));
}

// One 256-thread iteration (32 rows) of a 64-col fp16 K-major tile copy into SW128 smem.
__device__ __forceinline__ void cp_it(uint32_t dbase, const __half* __restrict__ src, int ld, int it) {
    int i = threadIdx.x + it * 256;
    int row = i >> 3, c = i & 7;
    uint32_t off = (uint32_t)(row * 128 + c * 16);
    cp16(dbase + swz(off), src + (size_t)row * ld + c * 8);
}

__device__ __forceinline__ void ldsm_x4(uint32_t* r, uint32_t addr) {
    asm volatile("ldmatrix.sync.aligned.m8n8.x4.shared.b16 {%0,%1,%2,%3}, [%4];"
                 : "=r"(r[0]), "=r"(r[1]), "=r"(r[2]), "=r"(r[3]) : "r"(addr));
}

__device__ __forceinline__ void mma_f16(float* c, const uint32_t* a, uint32_t b0, uint32_t b1) {
    asm volatile("mma.sync.aligned.m16n8k16.row.col.f32.f16.f16.f32 "
                 "{%0,%1,%2,%3}, {%4,%5,%6,%7}, {%8,%9}, {%0,%1,%2,%3};"
                 : "+f"(c[0]), "+f"(c[1]), "+f"(c[2]), "+f"(c[3])
                 : "r"(a[0]), "r"(a[1]), "r"(a[2]), "r"(a[3]), "r"(b0), "r"(b1));
}

// ===================== convert kernels =====================
__global__ void __launch_bounds__(256) conv_x_kernel(const float* __restrict__ x) {
    int idx4 = (blockIdx.x * 256 + threadIdx.x) * 4;
    float4 f = *reinterpret_cast<const float4*>(x + idx4);
    __half h[4] = {__float2half(f.x), __float2half(f.y), __float2half(f.z), __float2half(f.w)};
    *reinterpret_cast<uint2*>(g_x + idx4) = *reinterpret_cast<const uint2*>(h);
}

__global__ void __launch_bounds__(256) conv_gu_kernel(const float* __restrict__ Wg,
                                                      const float* __restrict__ Wu,
                                                      const int* __restrict__ aidx) {
    int idx4 = (blockIdx.x * 256 + threadIdx.x) * 4;   // < KPAD*HID
    int r = idx4 >> 12;
    int c = idx4 & 4095;
    __half hg[4] = {__half(0.f), __half(0.f), __half(0.f), __half(0.f)};
    __half hu[4] = {__half(0.f), __half(0.f), __half(0.f), __half(0.f)};
    if (r < KACT) {
        int a = aidx[r];
        float4 fg = *reinterpret_cast<const float4*>(Wg + (size_t)a * HID + c);
        float4 fu = *reinterpret_cast<const float4*>(Wu + (size_t)a * HID + c);
        hg[0] = __float2half(fg.x); hg[1] = __float2half(fg.y);
        hg[2] = __float2half(fg.z); hg[3] = __float2half(fg.w);
        hu[0] = __float2half(fu.x); hu[1] = __float2half(fu.y);
        hu[2] = __float2half(fu.z); hu[3] = __float2half(fu.w);
    }
    *reinterpret_cast<uint2*>(g_wg + idx4) = *reinterpret_cast<const uint2*>(hg);
    *reinterpret_cast<uint2*>(g_wu + idx4) = *reinterpret_cast<const uint2*>(hu);
}

__global__ void __launch_bounds__(256) conv_wd_kernel(const float* __restrict__ Wd,
                                                      const int* __restrict__ aidx) {
    int idx4 = (blockIdx.x * 256 + threadIdx.x) * 4;   // < HID*KPAD
    int hh = idx4 / KPAD;
    int r  = idx4 - hh * KPAD;
    __half v[4];
#pragma unroll
    for (int j = 0; j < 4; ++j) {
        int k = r + j;
        v[j] = (k < KACT) ? __float2half(Wd[(size_t)hh * WFULL + aidx[k]]) : __half(0.f);
    }
    *reinterpret_cast<uint2*>(g_wd + idx4) = *reinterpret_cast<const uint2*>(v);
}

// ===================== GEMM core config (R5 frontier point) =====================
// CTA 128x128, 256 threads, 8 warps (warp tile 32x[32g+32u] / 32x64).
// K-chunk 64, 3-stage cp.async, 2 CTAs/SM => 16 warps/SM.
// NEW: next-stage cp.async issued in QUARTERS inside the kk loop (spread LSU load),
// one commit per chunk, wait_group 1 at chunk top.
// Stage layout gemm1: x@0 (16K), wg@16K (8K), wu@24K (8K). Stage = 32K.
// Stage layout gemm2: h@0 (16K), wd@16K (16K). Stage = 32K.
#define STG      32768
#define SMEM_REQ (3 * STG + 1024)

// ===================== GEMM1: h = silu(x Wg^T) * (x Wu^T) =====================
// grid (64, 52).
__global__ void __launch_bounds__(256, 2) gemm1_kernel() {
    extern __shared__ char smem_raw[];
    char* smem = (char*)(((uintptr_t)smem_raw + 1023) & ~(uintptr_t)1023);
    uint32_t sb = smem_u32(smem);
    const int tid = threadIdx.x, l = tid & 31, wid = tid >> 5;
    const int wm = wid & 3, wn = wid >> 2;
    const int bM = blockIdx.x, bN = blockIdx.y;

    const __half* A  = g_x  + (size_t)bM * 128 * HID;
    const __half* Bg = g_wg + (size_t)bN * 64 * HID;
    const __half* Bu = g_wu + (size_t)bN * 64 * HID;

    float acc_g[2][4][4] = {};
    float acc_u[2][4][4] = {};

    auto load_stage = [&](int ch, int s) {   // prologue only: full stage
        uint32_t base = sb + s * STG;
#pragma unroll
        for (int it = 0; it < 4; ++it) cp_it(base, A + ch * 64, HID, it);
#pragma unroll
        for (int it = 0; it < 2; ++it) cp_it(base + 16384, Bg + ch * 64, HID, it);
#pragma unroll
        for (int it = 0; it < 2; ++it) cp_it(base + 24576, Bu + ch * 64, HID, it);
    };
    // quarter q of the stage loads (q = kk)
    auto load_quarter = [&](int ch, int s, int q) {
        uint32_t base = sb + s * STG;
        switch (q) {
        case 0: cp_it(base, A + ch * 64, HID, 0); cp_it(base, A + ch * 64, HID, 1); break;
        case 1: cp_it(base, A + ch * 64, HID, 2); cp_it(base, A + ch * 64, HID, 3); break;
        case 2: cp_it(base + 16384, Bg + ch * 64, HID, 0); cp_it(base + 16384, Bg + ch * 64, HID, 1); break;
        default: cp_it(base + 24576, Bu + ch * 64, HID, 0); cp_it(base + 24576, Bu + ch * 64, HID, 1); break;
        }
    };

    load_stage(0, 0); CP_COMMIT();
    load_stage(1, 1); CP_COMMIT();

    for (int ch = 0; ch < NCH1; ++ch) {
        CP_WAIT1();
        __syncthreads();
        uint32_t base = sb + (ch % 3) * STG;
        const bool pre = (ch + 2 < NCH1);
        const int s2 = (ch + 2) % 3;

#pragma unroll
        for (int kk = 0; kk < 4; ++kk) {
            uint32_t a[2][4];
#pragma unroll
            for (int mi = 0; mi < 2; ++mi) {
                uint32_t off = (uint32_t)((wm * 32 + mi * 16 + (l & 15)) * 128 + (kk * 2 + (l >> 4)) * 16);
                ldsm_x4(a[mi], base + swz(off));
            }
            uint32_t bg[2][4], bu[2][4];
#pragma unroll
            for (int ni = 0; ni < 2; ++ni) {
                uint32_t off = (uint32_t)((wn * 32 + ni * 16 + (l & 15)) * 128 + (kk * 2 + (l >> 4)) * 16);
                ldsm_x4(bg[ni], base + 16384 + swz(off));
                ldsm_x4(bu[ni], base + 24576 + swz(off));
            }
            if (pre) load_quarter(ch + 2, s2, kk);   // spread next-stage cp.async
#pragma unroll
            for (int mi = 0; mi < 2; ++mi)
#pragma unroll
                for (int ni = 0; ni < 2; ++ni)
#pragma unroll
                    for (int h = 0; h < 2; ++h) {
                        int nj = ni * 2 + h;
                        mma_f16(acc_g[mi][nj], a[mi], bg[ni][h], bg[ni][2 + h]);
                        mma_f16(acc_u[mi][nj], a[mi], bu[ni][h], bu[ni][2 + h]);
                    }
        }
        CP_COMMIT();   // one group per chunk (possibly empty near the end)
    }

    // Epilogue: h = silu(g)*u, fp16 store.
#pragma unroll
    for (int mi = 0; mi < 2; ++mi)
#pragma unroll
        for (int nj = 0; nj < 4; ++nj) {
            int r = bM * 128 + wm * 32 + mi * 16 + (l >> 2);
            int c = bN * 64 + wn * 32 + nj * 8 + (l & 3) * 2;
#pragma unroll
            for (int half = 0; half < 2; ++half) {
                float g0 = acc_g[mi][nj][half * 2 + 0], g1 = acc_g[mi][nj][half * 2 + 1];
                float u0 = acc_u[mi][nj][half * 2 + 0], u1 = acc_u[mi][nj][half * 2 + 1];
                float h0 = u0 * g0 / (1.f + __expf(-g0));
                float h1 = u1 * g1 / (1.f + __expf(-g1));
                __half2 ph; ph.x = __float2half(h0); ph.y = __float2half(h1);
                *reinterpret_cast<__half2*>(g_h + (size_t)(r + half * 8) * KPAD + c) = ph;
            }
        }
}

// ===================== GEMM2: out = h Wd^T =====================
// grid (64, 32): CTA 128x128, warp tile 32x64.
__global__ void __launch_bounds__(256, 2) gemm2_kernel(float* __restrict__ out) {
    extern __shared__ char smem_raw[];
    char* smem = (char*)(((uintptr_t)smem_raw + 1023) & ~(uintptr_t)1023);
    uint32_t sb = smem_u32(smem);
    const int tid = threadIdx.x, l = tid & 31, wid = tid >> 5;
    const int wm = wid & 3, wn = wid >> 2;
    const int bM = blockIdx.x, bN = blockIdx.y;

    const __half* A = g_h  + (size_t)bM * 128 * KPAD;
    const __half* B = g_wd + (size_t)bN * 128 * KPAD;

    float acc[2][8][4] = {};

    auto load_stage = [&](int ch, int s) {
        uint32_t base = sb + s * STG;
#pragma unroll
        for (int it = 0; it < 4; ++it) cp_it(base, A + ch * 64, KPAD, it);
#pragma unroll
        for (int it = 0; it < 4; ++it) cp_it(base + 16384, B + ch * 64, KPAD, it);
    };
    auto load_quarter = [&](int ch, int s, int q) {
        uint32_t base = sb + s * STG;
        switch (q) {
        case 0: cp_it(base, A + ch * 64, KPAD, 0); cp_it(base, A + ch * 64, KPAD, 1); break;
        case 1: cp_it(base, A + ch * 64, KPAD, 2); cp_it(base, A + ch * 64, KPAD, 3); break;
        case 2: cp_it(base + 16384, B + ch * 64, KPAD, 0); cp_it(base + 16384, B + ch * 64, KPAD, 1); break;
        default: cp_it(base + 16384, B + ch * 64, KPAD, 2); cp_it(base + 16384, B + ch * 64, KPAD, 3); break;
        }
    };

    load_stage(0, 0); CP_COMMIT();
    load_stage(1, 1); CP_COMMIT();

    for (int ch = 0; ch < NCH2; ++ch) {
        CP_WAIT1();
        __syncthreads();
        uint32_t base = sb + (ch % 3) * STG;
        const bool pre = (ch + 2 < NCH2);
        const int s2 = (ch + 2) % 3;

#pragma unroll
        for (int kk = 0; kk < 4; ++kk) {
            uint32_t a[2][4];
#pragma unroll
            for (int mi = 0; mi < 2; ++mi) {
                uint32_t off = (uint32_t)((wm * 32 + mi * 16 + (l & 15)) * 128 + (kk * 2 + (l >> 4)) * 16);
                ldsm_x4(a[mi], base + swz(off));
            }
            uint32_t b[4][4];
#pragma unroll
            for (int g4 = 0; g4 < 4; ++g4) {
                uint32_t off = (uint32_t)((wn * 64 + g4 * 16 + (l & 15)) * 128 + (kk * 2 + (l >> 4)) * 16);
                ldsm_x4(b[g4], base + 16384 + swz(off));
            }
            if (pre) load_quarter(ch + 2, s2, kk);
#pragma unroll
            for (int mi = 0; mi < 2; ++mi)
#pragma unroll
                for (int g4 = 0; g4 < 4; ++g4)
#pragma unroll
                    for (int h = 0; h < 2; ++h)
                        mma_f16(acc[mi][g4 * 2 + h], a[mi], b[g4][h], b[g4][2 + h]);
        }
        CP_COMMIT();
    }

    // Epilogue: fp32 float2 stores.
#pragma unroll
    for (int mi = 0; mi < 2; ++mi)
#pragma unroll
        for (int nj = 0; nj < 8; ++nj) {
            int r = bM * 128 + wm * 32 + mi * 16 + (l >> 2);
            int c = bN * 128 + wn * 64 + nj * 8 + (l & 3) * 2;
            float2 v0; v0.x = acc[mi][nj][0]; v0.y = acc[mi][nj][1];
            float2 v1; v1.x = acc[mi][nj][2]; v1.y = acc[mi][nj][3];
            *reinterpret_cast<float2*>(out + (size_t)r * HID + c) = v0;
            *reinterpret_cast<float2*>(out + (size_t)(r + 8) * HID + c) = v1;
        }
}

// ===================== launch =====================
extern "C" void kernel_launch(void* const* d_in, const int* in_sizes, int n_in,
                              void* d_out, int out_size) {
    const float* x  = (const float*)d_in[0];
    const float* Wg = (const float*)d_in[1];
    const float* Wu = (const float*)d_in[2];
    const float* Wd = (const float*)d_in[3];
    const int* aidx = (const int*)d_in[4];
    float* out = (float*)d_out;

    cudaFuncSetAttribute(gemm1_kernel, cudaFuncAttributeMaxDynamicSharedMemorySize, SMEM_REQ);
    cudaFuncSetAttribute(gemm2_kernel, cudaFuncAttributeMaxDynamicSharedMemorySize, SMEM_REQ);

    conv_x_kernel<<<(TOK * (size_t)HID) / 1024, 256>>>(x);
    conv_gu_kernel<<<((size_t)KPAD * HID) / 1024, 256>>>(Wg, Wu, aidx);
    conv_wd_kernel<<<((size_t)HID * KPAD) / 1024, 256>>>(Wd, aidx);
    gemm1_kernel<<<dim3(64, 52), 256, SMEM_REQ>>>();
    gemm2_kernel<<<dim3(64, 32), 256, SMEM_REQ>>>(out);
}